// round 15
// baseline (speedup 1.0000x reference)
#include <cuda_runtime.h>
#include <cfloat>
#include <math.h>

#define BB 4
#define NN 8192
#define CC 64
#define KK 16
#define HH 64
#define NPTS (BB*NN)

// ---------------- device scratch ------------------------------------------------
__device__ float4 g_P4[NPTS];                    // (x,y,z,|p|^2)
__device__ float  g_Sx[NPTS], g_Sy[NPTS], g_Sz[NPTS], g_Sq[NPTS];  // SoA coords
__device__ float  g_PT[(size_t)NPTS*192];        // [hc+b1 (64) | hn (64) | vn+bv (64)]
__device__ int    g_NB[NPTS*KK];                 // knn indices
__device__ float  g_stats[256];
__device__ float  g_ostats[128];
__device__ float  g_Opre[(size_t)NPTS*64];

// ---------------- f32x2 helpers -------------------------------------------------
typedef unsigned long long u64;
__device__ __forceinline__ u64 fma2(u64 a, u64 b, u64 c) {
    u64 d; asm("fma.rn.f32x2 %0,%1,%2,%3;" : "=l"(d) : "l"(a), "l"(b), "l"(c));
    return d;
}
__device__ __forceinline__ u64 add2(u64 a, u64 b) {
    u64 d; asm("add.rn.f32x2 %0,%1,%2;" : "=l"(d) : "l"(a), "l"(b));
    return d;
}
__device__ __forceinline__ u64 pk2(float v) {
    u64 d; asm("mov.b64 %0,{%1,%1};" : "=l"(d) : "f"(v));
    return d;
}
__device__ __forceinline__ u64 pkab(float a, float b) {
    u64 d; asm("mov.b64 %0,{%1,%2};" : "=l"(d) : "f"(a), "f"(b));
    return d;
}
__device__ __forceinline__ float2 unpk(u64 v) {
    float2 r; asm("mov.b64 {%0,%1},%2;" : "=f"(r.x), "=f"(r.y) : "l"(v));
    return r;
}

// ---------------- k0: pack xyz (AoS + SoA) + zero stats -------------------------
__global__ void k0(const float* __restrict__ xyz) {
    int p = blockIdx.x * blockDim.x + threadIdx.x;
    if (p < 256) g_stats[p] = 0.f;
    if (p < 128) g_ostats[p] = 0.f;
    if (p >= NPTS) return;
    int b = p >> 13, n = p & (NN - 1);
    const float* base = xyz + (size_t)b * 3 * NN + n;
    float x = base[0], y = base[NN], z = base[2 * NN];
    float w = x * x + y * y + z * z;
    g_P4[p] = make_float4(x, y, z, w);
    g_Sx[p] = x; g_Sy[p] = y; g_Sz[p] = z; g_Sq[p] = w;
}

// ---------------- k1: KNN, 4 warps split candidate range ------------------------
#define NWARP 4
#define RANGE 2048
#define TSH 128
#define BS  13      // odd -> no worse than natural 2-phase 64b smem access
#define VST 20      // top16 list stride (ints); 80B -> 16B-aligned LDS.128
__global__ void __launch_bounds__(128) k1() {
    __shared__ __align__(16) float sX[NWARP][TSH];
    __shared__ __align__(16) float sY[NWARP][TSH];
    __shared__ __align__(16) float sZ[NWARP][TSH];
    __shared__ __align__(16) float sWW[NWARP][TSH];
    __shared__ __align__(16) unsigned sVal[NWARP * 32 * VST];
    __shared__ int      sIdx[NWARP * 32 * VST];
    __shared__ __align__(8) float2 sBuf[NWARP * 32 * BS];

    int lane = threadIdx.x & 31;
    int wid  = threadIdx.x >> 5;
    int blk  = blockIdx.x;                // 1024 blocks
    int b    = blk >> 8;                  // 256 blocks per batch
    int n    = ((blk & 255) << 5) + lane;
    int p    = b * NN + n;

    float4 q = g_P4[p];
    float qw = q.w;
    u64 m2x = pk2(-2.f * q.x), m2y = pk2(-2.f * q.y), m2z = pk2(-2.f * q.z);

    int vb = (wid * 32 + lane) * VST;
    int bbuf = (wid * 32 + lane) * BS;
#pragma unroll
    for (int s = 0; s < 16; s++) {
        sVal[vb + s] = 0x7F7FFFF0u | (unsigned)s;
        sIdx[vb + s] = 0;
    }
    unsigned worstP = 0x7F7FFFFFu;
    float thr = __uint_as_float(0x7F7FFFF0u) - qw;   // t-domain threshold
    int cnt = 0;

    int cbase = wid * RANGE;
    for (int t0 = 0; t0 < RANGE; t0 += TSH) {
        __syncwarp();
        const float* bx = g_Sx + b * NN + cbase + t0;
        const float* by = g_Sy + b * NN + cbase + t0;
        const float* bz = g_Sz + b * NN + cbase + t0;
        const float* bw = g_Sq + b * NN + cbase + t0;
        {
            int o = lane * 4;
            *(float4*)(sX[wid]  + o) = *(const float4*)(bx + o);
            *(float4*)(sY[wid]  + o) = *(const float4*)(by + o);
            *(float4*)(sZ[wid]  + o) = *(const float4*)(bz + o);
            *(float4*)(sWW[wid] + o) = *(const float4*)(bw + o);
        }
        __syncwarp();

        for (int j = 0; j < TSH; j += 8) {
            ulonglong2 X0 = *(const ulonglong2*)(sX[wid]  + j);
            ulonglong2 Y0 = *(const ulonglong2*)(sY[wid]  + j);
            ulonglong2 Z0 = *(const ulonglong2*)(sZ[wid]  + j);
            ulonglong2 W0 = *(const ulonglong2*)(sWW[wid] + j);
            ulonglong2 X1 = *(const ulonglong2*)(sX[wid]  + j + 4);
            ulonglong2 Y1 = *(const ulonglong2*)(sY[wid]  + j + 4);
            ulonglong2 Z1 = *(const ulonglong2*)(sZ[wid]  + j + 4);
            ulonglong2 W1 = *(const ulonglong2*)(sWW[wid] + j + 4);
            u64 t0a = fma2(Z0.x, m2z, fma2(Y0.x, m2y, fma2(X0.x, m2x, W0.x)));
            u64 t0b = fma2(Z0.y, m2z, fma2(Y0.y, m2y, fma2(X0.y, m2x, W0.y)));
            u64 t1a = fma2(Z1.x, m2z, fma2(Y1.x, m2y, fma2(X1.x, m2x, W1.x)));
            u64 t1b = fma2(Z1.y, m2z, fma2(Y1.y, m2y, fma2(X1.y, m2x, W1.y)));
            float2 f01 = unpk(t0a), f23 = unpk(t0b), f45 = unpk(t1a), f67 = unpk(t1b);
            float m01 = fminf(f01.x, f01.y), m23 = fminf(f23.x, f23.y);
            float m45 = fminf(f45.x, f45.y), m67 = fminf(f67.x, f67.y);
            float mm = fminf(fminf(m01, m23), fminf(m45, m67));
            if (mm < thr) {
                float tt[8] = {f01.x, f01.y, f23.x, f23.y, f45.x, f45.y, f67.x, f67.y};
                int ib = cbase + t0 + j;
#pragma unroll
                for (int uu = 0; uu < 8; uu++) {
                    // unconditional store is safe: cnt only advances on pass
                    sBuf[bbuf + cnt] = make_float2(tt[uu], __int_as_float(ib + uu));
                    cnt += (tt[uu] < thr) ? 1 : 0;
                }
            }
            if (__any_sync(0xffffffffu, cnt >= BS - 7)) {
#pragma unroll 1
                for (int e = 0; e < cnt; e++) {
                    float2 pr = sBuf[bbuf + e];
                    if (pr.x < thr) {
                        float ts = fmaxf(pr.x + qw, 0.f);
                        unsigned slot = worstP & 0xFu;
                        sVal[vb + slot] = (__float_as_uint(ts) & 0xFFFFFFF0u) | slot;
                        sIdx[vb + slot] = __float_as_int(pr.y);
                        unsigned mmax = 0u;
                        const uint4* vp = (const uint4*)(sVal + vb);
#pragma unroll
                        for (int s4 = 0; s4 < 4; s4++) {
                            uint4 v = vp[s4];
                            mmax = max(mmax, max(max(v.x, v.y), max(v.z, v.w)));
                        }
                        worstP = mmax;
                        thr = __uint_as_float(mmax & 0xFFFFFFF0u) - qw;
                    }
                }
                cnt = 0;
            }
        }
    }

    // final flush of buffered candidates
#pragma unroll 1
    for (int e = 0; e < cnt; e++) {
        float2 pr = sBuf[bbuf + e];
        if (pr.x < thr) {
            float ts = fmaxf(pr.x + qw, 0.f);
            unsigned slot = worstP & 0xFu;
            sVal[vb + slot] = (__float_as_uint(ts) & 0xFFFFFFF0u) | slot;
            sIdx[vb + slot] = __float_as_int(pr.y);
            unsigned mmax = 0u;
            const uint4* vp = (const uint4*)(sVal + vb);
#pragma unroll
            for (int s4 = 0; s4 < 4; s4++) {
                uint4 v = vp[s4];
                mmax = max(mmax, max(max(v.x, v.y), max(v.z, v.w)));
            }
            worstP = mmax;
            thr = __uint_as_float(mmax & 0xFFFFFFF0u) - qw;
        }
    }

    // tree merge: round 1: w0<-w2, w1<-w3 ; round 2: w0<-w1
    float thrts = __uint_as_float(worstP & 0xFFFFFFF0u);
    __syncthreads();
    if (wid < 2) {
        int pb = ((wid + 2) * 32 + lane) * VST;
#pragma unroll
        for (int s = 0; s < 16; s++) {
            unsigned pv = sVal[pb + s];
            float pvts = __uint_as_float(pv & 0xFFFFFFF0u);
            if (pvts < thrts) {
                unsigned slot = worstP & 0xFu;
                sVal[vb + slot] = (pv & 0xFFFFFFF0u) | slot;
                sIdx[vb + slot] = sIdx[pb + s];
                unsigned mmax = 0u;
                const uint4* vp = (const uint4*)(sVal + vb);
#pragma unroll
                for (int s4 = 0; s4 < 4; s4++) {
                    uint4 v = vp[s4];
                    mmax = max(mmax, max(max(v.x, v.y), max(v.z, v.w)));
                }
                worstP = mmax;
                thrts = __uint_as_float(mmax & 0xFFFFFFF0u);
            }
        }
    }
    __syncthreads();
    if (wid == 0) {
        int pb = (32 + lane) * VST;
#pragma unroll
        for (int s = 0; s < 16; s++) {
            unsigned pv = sVal[pb + s];
            float pvts = __uint_as_float(pv & 0xFFFFFFF0u);
            if (pvts < thrts) {
                unsigned slot = worstP & 0xFu;
                sVal[vb + slot] = (pv & 0xFFFFFFF0u) | slot;
                sIdx[vb + slot] = sIdx[pb + s];
                unsigned mmax = 0u;
                const uint4* vp = (const uint4*)(sVal + vb);
#pragma unroll
                for (int s4 = 0; s4 < 4; s4++) {
                    uint4 v = vp[s4];
                    mmax = max(mmax, max(max(v.x, v.y), max(v.z, v.w)));
                }
                worstP = mmax;
                thrts = __uint_as_float(mmax & 0xFFFFFFF0u);
            }
        }
#pragma unroll
        for (int s = 0; s < 16; s++) g_NB[p * KK + s] = sIdx[vb + s];
    }
}

// ---------------- k2: per-point transforms, 3 passes of 64 outs -----------------
__global__ void __launch_bounds__(256) k2(const float* __restrict__ feats,
                   const float* __restrict__ W1, const float* __restrict__ b1,
                   const float* __restrict__ Wv, const float* __restrict__ bv) {
    __shared__ float sW[64][64];
    __shared__ float sF[64][64];
    int tid = threadIdx.x;
    int blk = blockIdx.x;
    int b   = blk >> 7;
    int n0  = (blk & 127) << 6;

    for (int e = tid; e < 1024; e += 256) {
        int c = e >> 4, v4 = e & 15;
        ((float4*)sF[c])[v4] =
            ((const float4*)(feats + (size_t)b * CC * NN + (size_t)c * NN + n0))[v4];
    }

    int og = tid & 15, ng = tid >> 4;

    for (int pp = 0; pp < 3; pp++) {
        __syncthreads();
        for (int e = tid; e < 4096; e += 256) {
            int ol = e & 63, c = e >> 6;
            float w;
            if (pp == 0)      w = W1[ol * 131 + c];
            else if (pp == 1) w = W1[ol * 131 + 64 + c];
            else              w = Wv[ol * 67 + c];
            sW[c][ol] = w;
        }
        __syncthreads();

        float4 a0 = make_float4(0.f,0.f,0.f,0.f), a1 = a0, a2 = a0, a3 = a0;
        for (int c = 0; c < 64; c++) {
            float4 w4 = *(const float4*)&sW[c][og * 4];
            float4 f4 = *(const float4*)&sF[c][ng * 4];
            a0.x = fmaf(w4.x, f4.x, a0.x); a0.y = fmaf(w4.y, f4.x, a0.y);
            a0.z = fmaf(w4.z, f4.x, a0.z); a0.w = fmaf(w4.w, f4.x, a0.w);
            a1.x = fmaf(w4.x, f4.y, a1.x); a1.y = fmaf(w4.y, f4.y, a1.y);
            a1.z = fmaf(w4.z, f4.y, a1.z); a1.w = fmaf(w4.w, f4.y, a1.w);
            a2.x = fmaf(w4.x, f4.z, a2.x); a2.y = fmaf(w4.y, f4.z, a2.y);
            a2.z = fmaf(w4.z, f4.z, a2.z); a2.w = fmaf(w4.w, f4.z, a2.w);
            a3.x = fmaf(w4.x, f4.w, a3.x); a3.y = fmaf(w4.y, f4.w, a3.y);
            a3.z = fmaf(w4.z, f4.w, a3.z); a3.w = fmaf(w4.w, f4.w, a3.w);
        }

        float4 bb = make_float4(0.f, 0.f, 0.f, 0.f);
        if (pp == 0) bb = *(const float4*)(b1 + og * 4);
        if (pp == 2) bb = *(const float4*)(bv + og * 4);
        int obase = pp * 64 + og * 4;
        float4 r;
        size_t pbase = (size_t)(b * NN + n0 + ng * 4);
        r = make_float4(a0.x+bb.x, a0.y+bb.y, a0.z+bb.z, a0.w+bb.w);
        *(float4*)(g_PT + (pbase + 0) * 192 + obase) = r;
        r = make_float4(a1.x+bb.x, a1.y+bb.y, a1.z+bb.z, a1.w+bb.w);
        *(float4*)(g_PT + (pbase + 1) * 192 + obase) = r;
        r = make_float4(a2.x+bb.x, a2.y+bb.y, a2.z+bb.z, a2.w+bb.w);
        *(float4*)(g_PT + (pbase + 2) * 192 + obase) = r;
        r = make_float4(a3.x+bb.x, a3.y+bb.y, a3.z+bb.z, a3.w+bb.w);
        *(float4*)(g_PT + (pbase + 3) * 192 + obase) = r;
    }
}

// ---------------- k3: BN stats (f32x2, chunked index prefetch, 5 blocks/SM) -----
__global__ void __launch_bounds__(256, 5) k3(const float* __restrict__ W1,
                                             const float* __restrict__ Wv) {
    __shared__ float sstat[256];
    int tid = threadIdx.x, lane = tid & 31, wid = tid >> 5;
    for (int e = tid; e < 256; e += 256) sstat[e] = 0.f;
    __syncthreads();

    int cc = lane * 2;   // channels cc, cc+1
    u64 w1x0 = pkab(W1[cc * 131 + 128], W1[(cc + 1) * 131 + 128]);
    u64 w1x1 = pkab(W1[cc * 131 + 129], W1[(cc + 1) * 131 + 129]);
    u64 w1x2 = pkab(W1[cc * 131 + 130], W1[(cc + 1) * 131 + 130]);
    u64 wvx0 = pkab(Wv[cc * 67 + 64],  Wv[(cc + 1) * 67 + 64]);
    u64 wvx1 = pkab(Wv[cc * 67 + 65],  Wv[(cc + 1) * 67 + 65]);
    u64 wvx2 = pkab(Wv[cc * 67 + 66],  Wv[(cc + 1) * 67 + 66]);

    u64 sh = 0, shq = 0, sv = 0, svq = 0;
    int gw = blockIdx.x * 8 + wid, nw = gridDim.x * 8;
    for (int p = gw; p < NPTS; p += nw) {
        int b = p >> 13;
        float4 q = g_P4[p];
        const int4* nb = (const int4*)(g_NB + p * KK);
        const float* ptp = g_PT + (size_t)p * 192;
        u64 hcp = *(const u64*)(ptp + cc);
#pragma unroll
        for (int half = 0; half < 2; half++) {
            int4 iA = nb[half * 2], iB = nb[half * 2 + 1];
            int mi[8] = {iA.x, iA.y, iA.z, iA.w, iB.x, iB.y, iB.z, iB.w};
#pragma unroll
            for (int k = 0; k < 8; k++) {
                int m = mi[k];
                float4 pm = g_P4[b * NN + m];
                u64 rxp = pk2(pm.x - q.x), ryp = pk2(pm.y - q.y), rzp = pk2(pm.z - q.z);
                const float* ptm = g_PT + (size_t)(b * NN + m) * 192;
                u64 hnp = *(const u64*)(ptm + 64 + cc);
                u64 vnp = *(const u64*)(ptm + 128 + cc);
                u64 h = fma2(rzp, w1x2, fma2(ryp, w1x1, fma2(rxp, w1x0, add2(hcp, hnp))));
                u64 v = fma2(rzp, wvx2, fma2(ryp, wvx1, fma2(rxp, wvx0, vnp)));
                sh = add2(sh, h); shq = fma2(h, h, shq);
                sv = add2(sv, v); svq = fma2(v, v, svq);
            }
        }
    }
    float2 fsh = unpk(sh), fshq = unpk(shq), fsv = unpk(sv), fsvq = unpk(svq);
    atomicAdd(&sstat[cc], fsh.x);       atomicAdd(&sstat[cc + 1], fsh.y);
    atomicAdd(&sstat[64 + cc], fshq.x); atomicAdd(&sstat[64 + cc + 1], fshq.y);
    atomicAdd(&sstat[128 + cc], fsv.x); atomicAdd(&sstat[128 + cc + 1], fsv.y);
    atomicAdd(&sstat[192 + cc], fsvq.x);atomicAdd(&sstat[192 + cc + 1], fsvq.y);
    __syncthreads();
    for (int e = tid; e < 256; e += 256) atomicAdd(&g_stats[e], sstat[e]);
}

// ---------------- k5: attention + value + out-conv (BN coefs computed inline) ---
__global__ void __launch_bounds__(256) k5(const float* __restrict__ W1,
                   const float* __restrict__ Wv,
                   const float* __restrict__ W2, const float* __restrict__ b2,
                   const float* __restrict__ Wo, const float* __restrict__ bo,
                   const float* __restrict__ g1, const float* __restrict__ be1,
                   const float* __restrict__ gv, const float* __restrict__ bev) {
    __shared__ float sWo[64][65];
    __shared__ float sOut[8][64];
    __shared__ float sstat[128];
    int tid = threadIdx.x, lane = tid & 31, wid = tid >> 5;

    for (int e = tid; e < 64 * 64; e += 256) {
        int j = e >> 6, c = e & 63;
        sWo[j][c] = Wo[c * 64 + j];
    }
    for (int e = tid; e < 128; e += 256) sstat[e] = 0.f;

    int cc = lane * 2;
    u64 w1x0 = pkab(W1[cc * 131 + 128], W1[(cc + 1) * 131 + 128]);
    u64 w1x1 = pkab(W1[cc * 131 + 129], W1[(cc + 1) * 131 + 129]);
    u64 w1x2 = pkab(W1[cc * 131 + 130], W1[(cc + 1) * 131 + 130]);
    u64 wvx0 = pkab(Wv[cc * 67 + 64],  Wv[(cc + 1) * 67 + 64]);
    u64 wvx1 = pkab(Wv[cc * 67 + 65],  Wv[(cc + 1) * 67 + 65]);
    u64 wvx2 = pkab(Wv[cc * 67 + 66],  Wv[(cc + 1) * 67 + 66]);

    // BN coefficients computed from finalized g_stats (k4 folded in)
    float cntk = (float)((size_t)NPTS * KK);
    float mh1 = g_stats[cc] / cntk,     mh2 = g_stats[cc + 1] / cntk;
    float vh1 = g_stats[64 + cc] / cntk - mh1 * mh1;
    float vh2 = g_stats[64 + cc + 1] / cntk - mh2 * mh2;
    float a1a = g1[cc] * rsqrtf(vh1 + 1e-5f), a1b = g1[cc + 1] * rsqrtf(vh2 + 1e-5f);
    float d1a = be1[cc] - a1a * mh1,          d1b = be1[cc + 1] - a1b * mh2;
    float mv1 = g_stats[128 + cc] / cntk,     mv2 = g_stats[128 + cc + 1] / cntk;
    float vv1s = g_stats[192 + cc] / cntk - mv1 * mv1;
    float vv2s = g_stats[192 + cc + 1] / cntk - mv2 * mv2;
    float ava = gv[cc] * rsqrtf(vv1s + 1e-5f), avb = gv[cc + 1] * rsqrtf(vv2s + 1e-5f);
    float dva = bev[cc] - ava * mv1,           dvb = bev[cc + 1] - avb * mv2;

    float w2a = W2[cc], w2b = W2[cc + 1];
    float b2v = b2[0];
    float boa = bo[cc], bob = bo[cc + 1];
    __syncthreads();

    float so1 = 0.f, so1q = 0.f, so2 = 0.f, so2q = 0.f;
    int gw = blockIdx.x * 8 + wid, nw = gridDim.x * 8;

    for (int p = gw; p < NPTS; p += nw) {
        int b = p >> 13;
        float4 q = g_P4[p];
        const int4* nb = (const int4*)(g_NB + p * KK);
        const float* ptp = g_PT + (size_t)p * 192;
        u64 hcp = *(const u64*)(ptp + cc);

        float logits[KK], vv1[KK], vv2[KK];
#pragma unroll
        for (int half = 0; half < 2; half++) {
            int4 iA = nb[half * 2], iB = nb[half * 2 + 1];
            int mi[8] = {iA.x, iA.y, iA.z, iA.w, iB.x, iB.y, iB.z, iB.w};
#pragma unroll
            for (int kk2 = 0; kk2 < 8; kk2++) {
                int k = half * 8 + kk2;
                int m = mi[kk2];
                float4 pm = g_P4[b * NN + m];
                u64 rxp = pk2(pm.x - q.x), ryp = pk2(pm.y - q.y), rzp = pk2(pm.z - q.z);
                const float* ptm = g_PT + (size_t)(b * NN + m) * 192;
                u64 hnp = *(const u64*)(ptm + 64 + cc);
                u64 vnp = *(const u64*)(ptm + 128 + cc);
                u64 h = fma2(rzp, w1x2, fma2(ryp, w1x1, fma2(rxp, w1x0, add2(hcp, hnp))));
                u64 v = fma2(rzp, wvx2, fma2(ryp, wvx1, fma2(rxp, wvx0, vnp)));
                float2 hf = unpk(h), vf = unpk(v);
                float hb1 = fmaxf(a1a * hf.x + d1a, 0.f);
                float hb2 = fmaxf(a1b * hf.y + d1b, 0.f);
                vv1[k] = fmaxf(ava * vf.x + dva, 0.f);
                vv2[k] = fmaxf(avb * vf.y + dvb, 0.f);
                float t = hb1 * w2a + hb2 * w2b;
#pragma unroll
                for (int off = 16; off > 0; off >>= 1) t += __shfl_xor_sync(0xffffffffu, t, off);
                logits[k] = t + b2v;
            }
        }
        float mx = logits[0];
#pragma unroll
        for (int k = 1; k < KK; k++) mx = fmaxf(mx, logits[k]);
        float ex[KK], se = 0.f;
#pragma unroll
        for (int k = 0; k < KK; k++) { ex[k] = __expf(logits[k] - mx); se += ex[k]; }
        float inv = 1.0f / se;
        float out1 = 0.f, out2 = 0.f;
#pragma unroll
        for (int k = 0; k < KK; k++) {
            float w = ex[k] * inv;
            out1 += w * vv1[k];
            out2 += w * vv2[k];
        }
        __syncwarp();
        sOut[wid][cc] = out1; sOut[wid][cc + 1] = out2;
        __syncwarp();
        float oo1 = boa, oo2 = bob;
#pragma unroll 8
        for (int j = 0; j < 64; j++) {
            float oj = sOut[wid][j];
            oo1 = fmaf(sWo[j][cc], oj, oo1);
            oo2 = fmaf(sWo[j][cc + 1], oj, oo2);
        }
        g_Opre[(size_t)p * 64 + cc] = oo1;
        g_Opre[(size_t)p * 64 + cc + 1] = oo2;
        so1 += oo1; so1q += oo1 * oo1;
        so2 += oo2; so2q += oo2 * oo2;
    }
    atomicAdd(&sstat[cc], so1);     atomicAdd(&sstat[64 + cc], so1q);
    atomicAdd(&sstat[cc + 1], so2); atomicAdd(&sstat[64 + cc + 1], so2q);
    __syncthreads();
    for (int e = tid; e < 128; e += 256) atomicAdd(&g_ostats[e], sstat[e]);
}

// ---------------- k7: BN + relu + residual + transpose (k6 folded in) -----------
__global__ void k7(const float* __restrict__ feats, float* __restrict__ out,
                   const float* __restrict__ go, const float* __restrict__ beo) {
    __shared__ float tile[32][65];
    __shared__ float sco[128];
    int blk = blockIdx.x;
    int b = blk >> 8;
    int n0 = (blk & 255) << 5;
    int tid = threadIdx.x;
    if (tid < 64) {
        float cntp = (float)NPTS;
        float m = g_ostats[tid] / cntp;
        float v = g_ostats[64 + tid] / cntp - m * m;
        float a = go[tid] * rsqrtf(v + 1e-5f);
        sco[tid] = a; sco[64 + tid] = beo[tid] - a * m;
    }
    for (int e = tid; e < 32 * 64; e += 256) {
        int pp = e >> 6, c = e & 63;
        tile[pp][c] = g_Opre[(size_t)(b * NN + n0 + pp) * 64 + c];
    }
    __syncthreads();
    for (int e = tid; e < 64 * 32; e += 256) {
        int c = e >> 5, j = e & 31;
        float val = sco[c] * tile[j][c] + sco[64 + c];
        val = fmaxf(val, 0.f) + feats[(size_t)b * CC * NN + (size_t)c * NN + n0 + j];
        out[(size_t)b * CC * NN + (size_t)c * NN + n0 + j] = val;
    }
}

// ---------------- launch --------------------------------------------------------
extern "C" void kernel_launch(void* const* d_in, const int* in_sizes, int n_in,
                              void* d_out, int out_size) {
    const float* xyz   = (const float*)d_in[0];
    const float* feats = (const float*)d_in[1];
    const float* W1    = (const float*)d_in[2];
    const float* b1    = (const float*)d_in[3];
    const float* g1    = (const float*)d_in[4];
    const float* be1   = (const float*)d_in[5];
    const float* W2    = (const float*)d_in[6];
    const float* b2    = (const float*)d_in[7];
    const float* Wv    = (const float*)d_in[8];
    const float* bv    = (const float*)d_in[9];
    const float* gv    = (const float*)d_in[10];
    const float* bev   = (const float*)d_in[11];
    const float* Wo    = (const float*)d_in[12];
    const float* bo    = (const float*)d_in[13];
    const float* go    = (const float*)d_in[14];
    const float* beo   = (const float*)d_in[15];
    float* out = (float*)d_out;

    // lazily-created side stream + events (no device memory involved)
    static cudaStream_t s2 = nullptr;
    static cudaEvent_t evFork = nullptr, evJoin = nullptr;
    if (s2 == nullptr) {
        cudaStreamCreateWithFlags(&s2, cudaStreamNonBlocking);
        cudaEventCreateWithFlags(&evFork, cudaEventDisableTiming);
        cudaEventCreateWithFlags(&evJoin, cudaEventDisableTiming);
    }

    // fork: k2 (depends only on feats) runs concurrently with k0+k1
    cudaEventRecord(evFork, 0);
    cudaStreamWaitEvent(s2, evFork, 0);
    k2<<<NPTS / 64, 256, 0, s2>>>(feats, W1, b1, Wv, bv);
    cudaEventRecord(evJoin, s2);

    k0<<<NPTS / 256, 256>>>(xyz);
    k1<<<NPTS / 32, 128>>>();

    // join: k3 needs both k1 (g_NB) and k2 (g_PT)
    cudaStreamWaitEvent(0, evJoin, 0);
    k3<<<1184, 256>>>(W1, Wv);
    k5<<<1184, 256>>>(W1, Wv, W2, b2, Wo, bo, g1, be1, gv, bev);
    k7<<<NPTS / 32, 256>>>(feats, out, go, beo);
}

// round 16
// speedup vs baseline: 1.0376x; 1.0376x over previous
#include <cuda_runtime.h>
#include <cfloat>
#include <math.h>

#define BB 4
#define NN 8192
#define CC 64
#define KK 16
#define HH 64
#define NPTS (BB*NN)

// ---------------- device scratch ------------------------------------------------
__device__ float4 g_P4[NPTS];                    // (x,y,z,|p|^2)
__device__ float  g_Sx[NPTS], g_Sy[NPTS], g_Sz[NPTS], g_Sq[NPTS];  // SoA coords
__device__ float  g_PT[(size_t)NPTS*192];        // [hc+b1 (64) | hn (64) | vn+bv (64)]
__device__ int    g_NB[NPTS*KK];                 // knn indices
__device__ float  g_stats[256];
__device__ float  g_ostats[128];
__device__ float  g_Opre[(size_t)NPTS*64];

// ---------------- f32x2 helpers -------------------------------------------------
typedef unsigned long long u64;
__device__ __forceinline__ u64 fma2(u64 a, u64 b, u64 c) {
    u64 d; asm("fma.rn.f32x2 %0,%1,%2,%3;" : "=l"(d) : "l"(a), "l"(b), "l"(c));
    return d;
}
__device__ __forceinline__ u64 add2(u64 a, u64 b) {
    u64 d; asm("add.rn.f32x2 %0,%1,%2;" : "=l"(d) : "l"(a), "l"(b));
    return d;
}
__device__ __forceinline__ u64 pk2(float v) {
    u64 d; asm("mov.b64 %0,{%1,%1};" : "=l"(d) : "f"(v));
    return d;
}
__device__ __forceinline__ u64 pkab(float a, float b) {
    u64 d; asm("mov.b64 %0,{%1,%2};" : "=l"(d) : "f"(a), "f"(b));
    return d;
}
__device__ __forceinline__ float2 unpk(u64 v) {
    float2 r; asm("mov.b64 {%0,%1},%2;" : "=f"(r.x), "=f"(r.y) : "l"(v));
    return r;
}

// ---------------- k0: pack xyz (AoS + SoA) + zero stats -------------------------
__global__ void k0(const float* __restrict__ xyz) {
    int p = blockIdx.x * blockDim.x + threadIdx.x;
    if (p < 256) g_stats[p] = 0.f;
    if (p < 128) g_ostats[p] = 0.f;
    if (p >= NPTS) return;
    int b = p >> 13, n = p & (NN - 1);
    const float* base = xyz + (size_t)b * 3 * NN + n;
    float x = base[0], y = base[NN], z = base[2 * NN];
    float w = x * x + y * y + z * z;
    g_P4[p] = make_float4(x, y, z, w);
    g_Sx[p] = x; g_Sy[p] = y; g_Sz[p] = z; g_Sq[p] = w;
}

// ---------------- k1: KNN, 4 warps split range + shared per-lane thresholds -----
#define NWARP 4
#define RANGE 2048
#define TSH 128
#define BS  13
#define VST 20
__global__ void __launch_bounds__(128) k1() {
    __shared__ __align__(16) float sX[NWARP][TSH];
    __shared__ __align__(16) float sY[NWARP][TSH];
    __shared__ __align__(16) float sZ[NWARP][TSH];
    __shared__ __align__(16) float sWW[NWARP][TSH];
    __shared__ __align__(16) unsigned sVal[NWARP * 32 * VST];
    __shared__ int      sIdx[NWARP * 32 * VST];
    __shared__ __align__(8) float2 sBuf[NWARP * 32 * BS];
    __shared__ float    sThr[NWARP * 32];   // per-warp per-lane local 16th-worst (t-domain)

    int lane = threadIdx.x & 31;
    int wid  = threadIdx.x >> 5;
    int blk  = blockIdx.x;                // 1024 blocks
    int b    = blk >> 8;                  // 256 blocks per batch
    int n    = ((blk & 255) << 5) + lane;
    int p    = b * NN + n;

    float4 q = g_P4[p];
    float qw = q.w;
    u64 m2x = pk2(-2.f * q.x), m2y = pk2(-2.f * q.y), m2z = pk2(-2.f * q.z);

    int vb = (wid * 32 + lane) * VST;
    int bbuf = (wid * 32 + lane) * BS;
#pragma unroll
    for (int s = 0; s < 16; s++) {
        sVal[vb + s] = 0x7F7FFFF0u | (unsigned)s;
        sIdx[vb + s] = 0;
    }
    sThr[wid * 32 + lane] = FLT_MAX;
    unsigned worstP = 0x7F7FFFFFu;
    float thrLoc = __uint_as_float(0x7F7FFFF0u) - qw;  // local-list threshold (t-domain)
    float thrE   = thrLoc;                             // effective = min(local, shared)
    int cnt = 0;
    __syncthreads();   // sThr rows initialized before anyone reads

    volatile float* vThr = sThr;
    int cbase = wid * RANGE;
    for (int t0 = 0; t0 < RANGE; t0 += TSH) {
        __syncwarp();
        const float* bx = g_Sx + b * NN + cbase + t0;
        const float* by = g_Sy + b * NN + cbase + t0;
        const float* bz = g_Sz + b * NN + cbase + t0;
        const float* bw = g_Sq + b * NN + cbase + t0;
        {
            int o = lane * 4;
            *(float4*)(sX[wid]  + o) = *(const float4*)(bx + o);
            *(float4*)(sY[wid]  + o) = *(const float4*)(by + o);
            *(float4*)(sZ[wid]  + o) = *(const float4*)(bz + o);
            *(float4*)(sWW[wid] + o) = *(const float4*)(bw + o);
        }
        __syncwarp();

        // refresh shared threshold (stale reads are only looser -> safe)
        {
            float s0 = vThr[lane], s1 = vThr[32 + lane];
            float s2 = vThr[64 + lane], s3 = vThr[96 + lane];
            float shMin = fminf(fminf(s0, s1), fminf(s2, s3));
            thrE = fminf(thrLoc, shMin);
        }

        for (int j = 0; j < TSH; j += 8) {
            ulonglong2 X0 = *(const ulonglong2*)(sX[wid]  + j);
            ulonglong2 Y0 = *(const ulonglong2*)(sY[wid]  + j);
            ulonglong2 Z0 = *(const ulonglong2*)(sZ[wid]  + j);
            ulonglong2 W0 = *(const ulonglong2*)(sWW[wid] + j);
            ulonglong2 X1 = *(const ulonglong2*)(sX[wid]  + j + 4);
            ulonglong2 Y1 = *(const ulonglong2*)(sY[wid]  + j + 4);
            ulonglong2 Z1 = *(const ulonglong2*)(sZ[wid]  + j + 4);
            ulonglong2 W1 = *(const ulonglong2*)(sWW[wid] + j + 4);
            u64 t0a = fma2(Z0.x, m2z, fma2(Y0.x, m2y, fma2(X0.x, m2x, W0.x)));
            u64 t0b = fma2(Z0.y, m2z, fma2(Y0.y, m2y, fma2(X0.y, m2x, W0.y)));
            u64 t1a = fma2(Z1.x, m2z, fma2(Y1.x, m2y, fma2(X1.x, m2x, W1.x)));
            u64 t1b = fma2(Z1.y, m2z, fma2(Y1.y, m2y, fma2(X1.y, m2x, W1.y)));
            float2 f01 = unpk(t0a), f23 = unpk(t0b), f45 = unpk(t1a), f67 = unpk(t1b);
            float m01 = fminf(f01.x, f01.y), m23 = fminf(f23.x, f23.y);
            float m45 = fminf(f45.x, f45.y), m67 = fminf(f67.x, f67.y);
            float mm = fminf(fminf(m01, m23), fminf(m45, m67));
            if (mm < thrE) {
                float tt[8] = {f01.x, f01.y, f23.x, f23.y, f45.x, f45.y, f67.x, f67.y};
                int ib = cbase + t0 + j;
#pragma unroll
                for (int uu = 0; uu < 8; uu++) {
                    sBuf[bbuf + cnt] = make_float2(tt[uu], __int_as_float(ib + uu));
                    cnt += (tt[uu] < thrE) ? 1 : 0;
                }
            }
            if (__any_sync(0xffffffffu, cnt >= BS - 7)) {
#pragma unroll 1
                for (int e = 0; e < cnt; e++) {
                    float2 pr = sBuf[bbuf + e];
                    if (pr.x < thrE) {
                        float ts = fmaxf(pr.x + qw, 0.f);
                        unsigned slot = worstP & 0xFu;
                        sVal[vb + slot] = (__float_as_uint(ts) & 0xFFFFFFF0u) | slot;
                        sIdx[vb + slot] = __float_as_int(pr.y);
                        unsigned mmax = 0u;
                        const uint4* vp = (const uint4*)(sVal + vb);
#pragma unroll
                        for (int s4 = 0; s4 < 4; s4++) {
                            uint4 v = vp[s4];
                            mmax = max(mmax, max(max(v.x, v.y), max(v.z, v.w)));
                        }
                        worstP = mmax;
                        thrLoc = __uint_as_float(mmax & 0xFFFFFFF0u) - qw;
                        thrE = fminf(thrE, thrLoc);
                    }
                }
                cnt = 0;
                sThr[wid * 32 + lane] = thrLoc;   // publish tightened local threshold
            }
        }
    }

    // final flush of buffered candidates
#pragma unroll 1
    for (int e = 0; e < cnt; e++) {
        float2 pr = sBuf[bbuf + e];
        if (pr.x < thrE) {
            float ts = fmaxf(pr.x + qw, 0.f);
            unsigned slot = worstP & 0xFu;
            sVal[vb + slot] = (__float_as_uint(ts) & 0xFFFFFFF0u) | slot;
            sIdx[vb + slot] = __float_as_int(pr.y);
            unsigned mmax = 0u;
            const uint4* vp = (const uint4*)(sVal + vb);
#pragma unroll
            for (int s4 = 0; s4 < 4; s4++) {
                uint4 v = vp[s4];
                mmax = max(mmax, max(max(v.x, v.y), max(v.z, v.w)));
            }
            worstP = mmax;
            thrLoc = __uint_as_float(mmax & 0xFFFFFFF0u) - qw;
            thrE = fminf(thrE, thrLoc);
        }
    }

    // tree merge: round 1: w0<-w2, w1<-w3 ; round 2: w0<-w1
    float thrts = __uint_as_float(worstP & 0xFFFFFFF0u);
    __syncthreads();
    if (wid < 2) {
        int pb = ((wid + 2) * 32 + lane) * VST;
#pragma unroll
        for (int s = 0; s < 16; s++) {
            unsigned pv = sVal[pb + s];
            float pvts = __uint_as_float(pv & 0xFFFFFFF0u);
            if (pvts < thrts) {
                unsigned slot = worstP & 0xFu;
                sVal[vb + slot] = (pv & 0xFFFFFFF0u) | slot;
                sIdx[vb + slot] = sIdx[pb + s];
                unsigned mmax = 0u;
                const uint4* vp = (const uint4*)(sVal + vb);
#pragma unroll
                for (int s4 = 0; s4 < 4; s4++) {
                    uint4 v = vp[s4];
                    mmax = max(mmax, max(max(v.x, v.y), max(v.z, v.w)));
                }
                worstP = mmax;
                thrts = __uint_as_float(mmax & 0xFFFFFFF0u);
            }
        }
    }
    __syncthreads();
    if (wid == 0) {
        int pb = (32 + lane) * VST;
#pragma unroll
        for (int s = 0; s < 16; s++) {
            unsigned pv = sVal[pb + s];
            float pvts = __uint_as_float(pv & 0xFFFFFFF0u);
            if (pvts < thrts) {
                unsigned slot = worstP & 0xFu;
                sVal[vb + slot] = (pv & 0xFFFFFFF0u) | slot;
                sIdx[vb + slot] = sIdx[pb + s];
                unsigned mmax = 0u;
                const uint4* vp = (const uint4*)(sVal + vb);
#pragma unroll
                for (int s4 = 0; s4 < 4; s4++) {
                    uint4 v = vp[s4];
                    mmax = max(mmax, max(max(v.x, v.y), max(v.z, v.w)));
                }
                worstP = mmax;
                thrts = __uint_as_float(mmax & 0xFFFFFFF0u);
            }
        }
#pragma unroll
        for (int s = 0; s < 16; s++) g_NB[p * KK + s] = sIdx[vb + s];
    }
}

// ---------------- k2: per-point transforms, 3 passes of 64 outs -----------------
__global__ void __launch_bounds__(256) k2(const float* __restrict__ feats,
                   const float* __restrict__ W1, const float* __restrict__ b1,
                   const float* __restrict__ Wv, const float* __restrict__ bv) {
    __shared__ float sW[64][64];
    __shared__ float sF[64][64];
    int tid = threadIdx.x;
    int blk = blockIdx.x;
    int b   = blk >> 7;
    int n0  = (blk & 127) << 6;

    for (int e = tid; e < 1024; e += 256) {
        int c = e >> 4, v4 = e & 15;
        ((float4*)sF[c])[v4] =
            ((const float4*)(feats + (size_t)b * CC * NN + (size_t)c * NN + n0))[v4];
    }

    int og = tid & 15, ng = tid >> 4;

    for (int pp = 0; pp < 3; pp++) {
        __syncthreads();
        for (int e = tid; e < 4096; e += 256) {
            int ol = e & 63, c = e >> 6;
            float w;
            if (pp == 0)      w = W1[ol * 131 + c];
            else if (pp == 1) w = W1[ol * 131 + 64 + c];
            else              w = Wv[ol * 67 + c];
            sW[c][ol] = w;
        }
        __syncthreads();

        float4 a0 = make_float4(0.f,0.f,0.f,0.f), a1 = a0, a2 = a0, a3 = a0;
        for (int c = 0; c < 64; c++) {
            float4 w4 = *(const float4*)&sW[c][og * 4];
            float4 f4 = *(const float4*)&sF[c][ng * 4];
            a0.x = fmaf(w4.x, f4.x, a0.x); a0.y = fmaf(w4.y, f4.x, a0.y);
            a0.z = fmaf(w4.z, f4.x, a0.z); a0.w = fmaf(w4.w, f4.x, a0.w);
            a1.x = fmaf(w4.x, f4.y, a1.x); a1.y = fmaf(w4.y, f4.y, a1.y);
            a1.z = fmaf(w4.z, f4.y, a1.z); a1.w = fmaf(w4.w, f4.y, a1.w);
            a2.x = fmaf(w4.x, f4.z, a2.x); a2.y = fmaf(w4.y, f4.z, a2.y);
            a2.z = fmaf(w4.z, f4.z, a2.z); a2.w = fmaf(w4.w, f4.z, a2.w);
            a3.x = fmaf(w4.x, f4.w, a3.x); a3.y = fmaf(w4.y, f4.w, a3.y);
            a3.z = fmaf(w4.z, f4.w, a3.z); a3.w = fmaf(w4.w, f4.w, a3.w);
        }

        float4 bb = make_float4(0.f, 0.f, 0.f, 0.f);
        if (pp == 0) bb = *(const float4*)(b1 + og * 4);
        if (pp == 2) bb = *(const float4*)(bv + og * 4);
        int obase = pp * 64 + og * 4;
        float4 r;
        size_t pbase = (size_t)(b * NN + n0 + ng * 4);
        r = make_float4(a0.x+bb.x, a0.y+bb.y, a0.z+bb.z, a0.w+bb.w);
        *(float4*)(g_PT + (pbase + 0) * 192 + obase) = r;
        r = make_float4(a1.x+bb.x, a1.y+bb.y, a1.z+bb.z, a1.w+bb.w);
        *(float4*)(g_PT + (pbase + 1) * 192 + obase) = r;
        r = make_float4(a2.x+bb.x, a2.y+bb.y, a2.z+bb.z, a2.w+bb.w);
        *(float4*)(g_PT + (pbase + 2) * 192 + obase) = r;
        r = make_float4(a3.x+bb.x, a3.y+bb.y, a3.z+bb.z, a3.w+bb.w);
        *(float4*)(g_PT + (pbase + 3) * 192 + obase) = r;
    }
}

// ---------------- k3: BN stats for h and v (f32x2, channel pairs) ---------------
__global__ void __launch_bounds__(256) k3(const float* __restrict__ W1,
                                          const float* __restrict__ Wv) {
    __shared__ float sstat[256];
    int tid = threadIdx.x, lane = tid & 31, wid = tid >> 5;
    for (int e = tid; e < 256; e += 256) sstat[e] = 0.f;
    __syncthreads();

    int cc = lane * 2;   // channels cc, cc+1
    u64 w1x0 = pkab(W1[cc * 131 + 128], W1[(cc + 1) * 131 + 128]);
    u64 w1x1 = pkab(W1[cc * 131 + 129], W1[(cc + 1) * 131 + 129]);
    u64 w1x2 = pkab(W1[cc * 131 + 130], W1[(cc + 1) * 131 + 130]);
    u64 wvx0 = pkab(Wv[cc * 67 + 64],  Wv[(cc + 1) * 67 + 64]);
    u64 wvx1 = pkab(Wv[cc * 67 + 65],  Wv[(cc + 1) * 67 + 65]);
    u64 wvx2 = pkab(Wv[cc * 67 + 66],  Wv[(cc + 1) * 67 + 66]);

    u64 sh = 0, shq = 0, sv = 0, svq = 0;
    int gw = blockIdx.x * 8 + wid, nw = gridDim.x * 8;
    for (int p = gw; p < NPTS; p += nw) {
        int b = p >> 13;
        float4 q = g_P4[p];
        const int4* nb = (const int4*)(g_NB + p * KK);
        int4 iA = nb[0], iB = nb[1], iC = nb[2], iD = nb[3];
        int mi[16] = {iA.x, iA.y, iA.z, iA.w, iB.x, iB.y, iB.z, iB.w,
                      iC.x, iC.y, iC.z, iC.w, iD.x, iD.y, iD.z, iD.w};
        const float* ptp = g_PT + (size_t)p * 192;
        u64 hcp = *(const u64*)(ptp + cc);
#pragma unroll
        for (int k = 0; k < KK; k++) {
            int m = mi[k];
            float4 pm = g_P4[b * NN + m];
            u64 rxp = pk2(pm.x - q.x), ryp = pk2(pm.y - q.y), rzp = pk2(pm.z - q.z);
            const float* ptm = g_PT + (size_t)(b * NN + m) * 192;
            u64 hnp = *(const u64*)(ptm + 64 + cc);
            u64 vnp = *(const u64*)(ptm + 128 + cc);
            u64 h = fma2(rzp, w1x2, fma2(ryp, w1x1, fma2(rxp, w1x0, add2(hcp, hnp))));
            u64 v = fma2(rzp, wvx2, fma2(ryp, wvx1, fma2(rxp, wvx0, vnp)));
            sh = add2(sh, h); shq = fma2(h, h, shq);
            sv = add2(sv, v); svq = fma2(v, v, svq);
        }
    }
    float2 fsh = unpk(sh), fshq = unpk(shq), fsv = unpk(sv), fsvq = unpk(svq);
    atomicAdd(&sstat[cc], fsh.x);       atomicAdd(&sstat[cc + 1], fsh.y);
    atomicAdd(&sstat[64 + cc], fshq.x); atomicAdd(&sstat[64 + cc + 1], fshq.y);
    atomicAdd(&sstat[128 + cc], fsv.x); atomicAdd(&sstat[128 + cc + 1], fsv.y);
    atomicAdd(&sstat[192 + cc], fsvq.x);atomicAdd(&sstat[192 + cc + 1], fsvq.y);
    __syncthreads();
    for (int e = tid; e < 256; e += 256) atomicAdd(&g_stats[e], sstat[e]);
}

// ---------------- k5: attention + value + out-conv (BN coefs computed inline) ---
__global__ void __launch_bounds__(256) k5(const float* __restrict__ W1,
                   const float* __restrict__ Wv,
                   const float* __restrict__ W2, const float* __restrict__ b2,
                   const float* __restrict__ Wo, const float* __restrict__ bo,
                   const float* __restrict__ g1, const float* __restrict__ be1,
                   const float* __restrict__ gv, const float* __restrict__ bev) {
    __shared__ float sWo[64][65];
    __shared__ float sOut[8][64];
    __shared__ float sstat[128];
    int tid = threadIdx.x, lane = tid & 31, wid = tid >> 5;

    for (int e = tid; e < 64 * 64; e += 256) {
        int j = e >> 6, c = e & 63;
        sWo[j][c] = Wo[c * 64 + j];
    }
    for (int e = tid; e < 128; e += 256) sstat[e] = 0.f;

    int cc = lane * 2;
    u64 w1x0 = pkab(W1[cc * 131 + 128], W1[(cc + 1) * 131 + 128]);
    u64 w1x1 = pkab(W1[cc * 131 + 129], W1[(cc + 1) * 131 + 129]);
    u64 w1x2 = pkab(W1[cc * 131 + 130], W1[(cc + 1) * 131 + 130]);
    u64 wvx0 = pkab(Wv[cc * 67 + 64],  Wv[(cc + 1) * 67 + 64]);
    u64 wvx1 = pkab(Wv[cc * 67 + 65],  Wv[(cc + 1) * 67 + 65]);
    u64 wvx2 = pkab(Wv[cc * 67 + 66],  Wv[(cc + 1) * 67 + 66]);

    // BN coefficients computed from finalized g_stats (k4 folded in)
    float cntk = (float)((size_t)NPTS * KK);
    float mh1 = g_stats[cc] / cntk,     mh2 = g_stats[cc + 1] / cntk;
    float vh1 = g_stats[64 + cc] / cntk - mh1 * mh1;
    float vh2 = g_stats[64 + cc + 1] / cntk - mh2 * mh2;
    float a1a = g1[cc] * rsqrtf(vh1 + 1e-5f), a1b = g1[cc + 1] * rsqrtf(vh2 + 1e-5f);
    float d1a = be1[cc] - a1a * mh1,          d1b = be1[cc + 1] - a1b * mh2;
    float mv1 = g_stats[128 + cc] / cntk,     mv2 = g_stats[128 + cc + 1] / cntk;
    float vv1s = g_stats[192 + cc] / cntk - mv1 * mv1;
    float vv2s = g_stats[192 + cc + 1] / cntk - mv2 * mv2;
    float ava = gv[cc] * rsqrtf(vv1s + 1e-5f), avb = gv[cc + 1] * rsqrtf(vv2s + 1e-5f);
    float dva = bev[cc] - ava * mv1,           dvb = bev[cc + 1] - avb * mv2;

    float w2a = W2[cc], w2b = W2[cc + 1];
    float b2v = b2[0];
    float boa = bo[cc], bob = bo[cc + 1];
    __syncthreads();

    float so1 = 0.f, so1q = 0.f, so2 = 0.f, so2q = 0.f;
    int gw = blockIdx.x * 8 + wid, nw = gridDim.x * 8;

    for (int p = gw; p < NPTS; p += nw) {
        int b = p >> 13;
        float4 q = g_P4[p];
        const int4* nb = (const int4*)(g_NB + p * KK);
        int4 iA = nb[0], iB = nb[1], iC = nb[2], iD = nb[3];
        int mi[16] = {iA.x, iA.y, iA.z, iA.w, iB.x, iB.y, iB.z, iB.w,
                      iC.x, iC.y, iC.z, iC.w, iD.x, iD.y, iD.z, iD.w};
        const float* ptp = g_PT + (size_t)p * 192;
        u64 hcp = *(const u64*)(ptp + cc);

        float logits[KK], vv1[KK], vv2[KK];
#pragma unroll
        for (int k = 0; k < KK; k++) {
            int m = mi[k];
            float4 pm = g_P4[b * NN + m];
            u64 rxp = pk2(pm.x - q.x), ryp = pk2(pm.y - q.y), rzp = pk2(pm.z - q.z);
            const float* ptm = g_PT + (size_t)(b * NN + m) * 192;
            u64 hnp = *(const u64*)(ptm + 64 + cc);
            u64 vnp = *(const u64*)(ptm + 128 + cc);
            u64 h = fma2(rzp, w1x2, fma2(ryp, w1x1, fma2(rxp, w1x0, add2(hcp, hnp))));
            u64 v = fma2(rzp, wvx2, fma2(ryp, wvx1, fma2(rxp, wvx0, vnp)));
            float2 hf = unpk(h), vf = unpk(v);
            float hb1 = fmaxf(a1a * hf.x + d1a, 0.f);
            float hb2 = fmaxf(a1b * hf.y + d1b, 0.f);
            vv1[k] = fmaxf(ava * vf.x + dva, 0.f);
            vv2[k] = fmaxf(avb * vf.y + dvb, 0.f);
            float t = hb1 * w2a + hb2 * w2b;
#pragma unroll
            for (int off = 16; off > 0; off >>= 1) t += __shfl_xor_sync(0xffffffffu, t, off);
            logits[k] = t + b2v;
        }
        float mx = logits[0];
#pragma unroll
        for (int k = 1; k < KK; k++) mx = fmaxf(mx, logits[k]);
        float ex[KK], se = 0.f;
#pragma unroll
        for (int k = 0; k < KK; k++) { ex[k] = __expf(logits[k] - mx); se += ex[k]; }
        float inv = 1.0f / se;
        float out1 = 0.f, out2 = 0.f;
#pragma unroll
        for (int k = 0; k < KK; k++) {
            float w = ex[k] * inv;
            out1 += w * vv1[k];
            out2 += w * vv2[k];
        }
        __syncwarp();
        sOut[wid][cc] = out1; sOut[wid][cc + 1] = out2;
        __syncwarp();
        float oo1 = boa, oo2 = bob;
#pragma unroll 8
        for (int j = 0; j < 64; j++) {
            float oj = sOut[wid][j];
            oo1 = fmaf(sWo[j][cc], oj, oo1);
            oo2 = fmaf(sWo[j][cc + 1], oj, oo2);
        }
        g_Opre[(size_t)p * 64 + cc] = oo1;
        g_Opre[(size_t)p * 64 + cc + 1] = oo2;
        so1 += oo1; so1q += oo1 * oo1;
        so2 += oo2; so2q += oo2 * oo2;
    }
    atomicAdd(&sstat[cc], so1);     atomicAdd(&sstat[64 + cc], so1q);
    atomicAdd(&sstat[cc + 1], so2); atomicAdd(&sstat[64 + cc + 1], so2q);
    __syncthreads();
    for (int e = tid; e < 128; e += 256) atomicAdd(&g_ostats[e], sstat[e]);
}

// ---------------- k7: BN + relu + residual + transpose (k6 folded in) -----------
__global__ void k7(const float* __restrict__ feats, float* __restrict__ out,
                   const float* __restrict__ go, const float* __restrict__ beo) {
    __shared__ float tile[32][65];
    __shared__ float sco[128];
    int blk = blockIdx.x;
    int b = blk >> 8;
    int n0 = (blk & 255) << 5;
    int tid = threadIdx.x;
    if (tid < 64) {
        float cntp = (float)NPTS;
        float m = g_ostats[tid] / cntp;
        float v = g_ostats[64 + tid] / cntp - m * m;
        float a = go[tid] * rsqrtf(v + 1e-5f);
        sco[tid] = a; sco[64 + tid] = beo[tid] - a * m;
    }
    for (int e = tid; e < 32 * 64; e += 256) {
        int pp = e >> 6, c = e & 63;
        tile[pp][c] = g_Opre[(size_t)(b * NN + n0 + pp) * 64 + c];
    }
    __syncthreads();
    for (int e = tid; e < 64 * 32; e += 256) {
        int c = e >> 5, j = e & 31;
        float val = sco[c] * tile[j][c] + sco[64 + c];
        val = fmaxf(val, 0.f) + feats[(size_t)b * CC * NN + (size_t)c * NN + n0 + j];
        out[(size_t)b * CC * NN + (size_t)c * NN + n0 + j] = val;
    }
}

// ---------------- launch --------------------------------------------------------
extern "C" void kernel_launch(void* const* d_in, const int* in_sizes, int n_in,
                              void* d_out, int out_size) {
    const float* xyz   = (const float*)d_in[0];
    const float* feats = (const float*)d_in[1];
    const float* W1    = (const float*)d_in[2];
    const float* b1    = (const float*)d_in[3];
    const float* g1    = (const float*)d_in[4];
    const float* be1   = (const float*)d_in[5];
    const float* W2    = (const float*)d_in[6];
    const float* b2    = (const float*)d_in[7];
    const float* Wv    = (const float*)d_in[8];
    const float* bv    = (const float*)d_in[9];
    const float* gv    = (const float*)d_in[10];
    const float* bev   = (const float*)d_in[11];
    const float* Wo    = (const float*)d_in[12];
    const float* bo    = (const float*)d_in[13];
    const float* go    = (const float*)d_in[14];
    const float* beo   = (const float*)d_in[15];
    float* out = (float*)d_out;

    // lazily-created side stream + events (no device memory involved)
    static cudaStream_t s2 = nullptr;
    static cudaEvent_t evFork = nullptr, evJoin = nullptr;
    if (s2 == nullptr) {
        cudaStreamCreateWithFlags(&s2, cudaStreamNonBlocking);
        cudaEventCreateWithFlags(&evFork, cudaEventDisableTiming);
        cudaEventCreateWithFlags(&evJoin, cudaEventDisableTiming);
    }

    // fork: k2 (depends only on feats) runs concurrently with k0+k1
    cudaEventRecord(evFork, 0);
    cudaStreamWaitEvent(s2, evFork, 0);
    k2<<<NPTS / 64, 256, 0, s2>>>(feats, W1, b1, Wv, bv);
    cudaEventRecord(evJoin, s2);

    k0<<<NPTS / 256, 256>>>(xyz);
    k1<<<NPTS / 32, 128>>>();

    // join: k3 needs both k1 (g_NB) and k2 (g_PT)
    cudaStreamWaitEvent(0, evJoin, 0);
    k3<<<1184, 256>>>(W1, Wv);
    k5<<<1184, 256>>>(W1, Wv, W2, b2, Wo, bo, g1, be1, gv, bev);
    k7<<<NPTS / 32, 256>>>(feats, out, go, beo);
}

// round 17
// speedup vs baseline: 1.0632x; 1.0247x over previous
#include <cuda_runtime.h>
#include <cfloat>
#include <math.h>

#define BB 4
#define NN 8192
#define CC 64
#define KK 16
#define HH 64
#define NPTS (BB*NN)

// ---------------- device scratch ------------------------------------------------
__device__ float4 g_P4[NPTS];                    // (x,y,z,|p|^2)
__device__ float  g_Sx[NPTS], g_Sy[NPTS], g_Sz[NPTS], g_Sq[NPTS];  // SoA coords
__device__ float  g_PT[(size_t)NPTS*192];        // [hc+b1 (64) | hn (64) | vn+bv (64)]
__device__ int    g_NB[NPTS*KK];                 // knn indices
__device__ float  g_stats[256];
__device__ float  g_ostats[128];
__device__ float  g_Opre[(size_t)NPTS*64];

// ---------------- f32x2 helpers -------------------------------------------------
typedef unsigned long long u64;
__device__ __forceinline__ u64 fma2(u64 a, u64 b, u64 c) {
    u64 d; asm("fma.rn.f32x2 %0,%1,%2,%3;" : "=l"(d) : "l"(a), "l"(b), "l"(c));
    return d;
}
__device__ __forceinline__ u64 add2(u64 a, u64 b) {
    u64 d; asm("add.rn.f32x2 %0,%1,%2;" : "=l"(d) : "l"(a), "l"(b));
    return d;
}
__device__ __forceinline__ u64 pk2(float v) {
    u64 d; asm("mov.b64 %0,{%1,%1};" : "=l"(d) : "f"(v));
    return d;
}
__device__ __forceinline__ u64 pkab(float a, float b) {
    u64 d; asm("mov.b64 %0,{%1,%2};" : "=l"(d) : "f"(a), "f"(b));
    return d;
}
__device__ __forceinline__ float2 unpk(u64 v) {
    float2 r; asm("mov.b64 {%0,%1},%2;" : "=f"(r.x), "=f"(r.y) : "l"(v));
    return r;
}

// ---------------- k0: pack xyz (AoS + SoA) + zero stats -------------------------
__global__ void k0(const float* __restrict__ xyz) {
    int p = blockIdx.x * blockDim.x + threadIdx.x;
    if (p < 256) g_stats[p] = 0.f;
    if (p < 128) g_ostats[p] = 0.f;
    if (p >= NPTS) return;
    int b = p >> 13, n = p & (NN - 1);
    const float* base = xyz + (size_t)b * 3 * NN + n;
    float x = base[0], y = base[NN], z = base[2 * NN];
    float w = x * x + y * y + z * z;
    g_P4[p] = make_float4(x, y, z, w);
    g_Sx[p] = x; g_Sy[p] = y; g_Sz[p] = z; g_Sq[p] = w;
}

// ---------------- k1: KNN, 4 warps split range + shared per-lane thresholds -----
#define NWARP 4
#define RANGE 2048
#define TSH 128
#define BS  13
#define VST 20
__global__ void __launch_bounds__(128) k1() {
    __shared__ __align__(16) float sX[NWARP][TSH];
    __shared__ __align__(16) float sY[NWARP][TSH];
    __shared__ __align__(16) float sZ[NWARP][TSH];
    __shared__ __align__(16) float sWW[NWARP][TSH];
    __shared__ __align__(16) unsigned sVal[NWARP * 32 * VST];
    __shared__ int      sIdx[NWARP * 32 * VST];
    __shared__ __align__(8) float2 sBuf[NWARP * 32 * BS];
    __shared__ float    sThr[NWARP * 32];   // per-warp per-lane local 16th-worst (t-domain)

    int lane = threadIdx.x & 31;
    int wid  = threadIdx.x >> 5;
    int blk  = blockIdx.x;                // 1024 blocks
    int b    = blk >> 8;                  // 256 blocks per batch
    int n    = ((blk & 255) << 5) + lane;
    int p    = b * NN + n;

    float4 q = g_P4[p];
    float qw = q.w;
    u64 m2x = pk2(-2.f * q.x), m2y = pk2(-2.f * q.y), m2z = pk2(-2.f * q.z);

    int vb = (wid * 32 + lane) * VST;
    int bbuf = (wid * 32 + lane) * BS;
#pragma unroll
    for (int s = 0; s < 16; s++) {
        sVal[vb + s] = 0x7F7FFFF0u | (unsigned)s;
        sIdx[vb + s] = 0;
    }
    sThr[wid * 32 + lane] = FLT_MAX;
    unsigned worstP = 0x7F7FFFFFu;
    float thrLoc = __uint_as_float(0x7F7FFFF0u) - qw;  // local-list threshold (t-domain)
    float thrE   = thrLoc;                             // effective = min(local, shared)
    int cnt = 0;
    __syncthreads();   // sThr rows initialized before anyone reads

    volatile float* vThr = sThr;
    int cbase = wid * RANGE;
    for (int t0 = 0; t0 < RANGE; t0 += TSH) {
        __syncwarp();
        const float* bx = g_Sx + b * NN + cbase + t0;
        const float* by = g_Sy + b * NN + cbase + t0;
        const float* bz = g_Sz + b * NN + cbase + t0;
        const float* bw = g_Sq + b * NN + cbase + t0;
        {
            int o = lane * 4;
            *(float4*)(sX[wid]  + o) = *(const float4*)(bx + o);
            *(float4*)(sY[wid]  + o) = *(const float4*)(by + o);
            *(float4*)(sZ[wid]  + o) = *(const float4*)(bz + o);
            *(float4*)(sWW[wid] + o) = *(const float4*)(bw + o);
        }
        __syncwarp();

        // refresh shared threshold (stale reads are only looser -> safe)
        {
            float s0 = vThr[lane], s1 = vThr[32 + lane];
            float s2 = vThr[64 + lane], s3 = vThr[96 + lane];
            float shMin = fminf(fminf(s0, s1), fminf(s2, s3));
            thrE = fminf(thrLoc, shMin);
        }

        for (int j = 0; j < TSH; j += 8) {
            ulonglong2 X0 = *(const ulonglong2*)(sX[wid]  + j);
            ulonglong2 Y0 = *(const ulonglong2*)(sY[wid]  + j);
            ulonglong2 Z0 = *(const ulonglong2*)(sZ[wid]  + j);
            ulonglong2 W0 = *(const ulonglong2*)(sWW[wid] + j);
            ulonglong2 X1 = *(const ulonglong2*)(sX[wid]  + j + 4);
            ulonglong2 Y1 = *(const ulonglong2*)(sY[wid]  + j + 4);
            ulonglong2 Z1 = *(const ulonglong2*)(sZ[wid]  + j + 4);
            ulonglong2 W1 = *(const ulonglong2*)(sWW[wid] + j + 4);
            u64 t0a = fma2(Z0.x, m2z, fma2(Y0.x, m2y, fma2(X0.x, m2x, W0.x)));
            u64 t0b = fma2(Z0.y, m2z, fma2(Y0.y, m2y, fma2(X0.y, m2x, W0.y)));
            u64 t1a = fma2(Z1.x, m2z, fma2(Y1.x, m2y, fma2(X1.x, m2x, W1.x)));
            u64 t1b = fma2(Z1.y, m2z, fma2(Y1.y, m2y, fma2(X1.y, m2x, W1.y)));
            float2 f01 = unpk(t0a), f23 = unpk(t0b), f45 = unpk(t1a), f67 = unpk(t1b);
            float m01 = fminf(f01.x, f01.y), m23 = fminf(f23.x, f23.y);
            float m45 = fminf(f45.x, f45.y), m67 = fminf(f67.x, f67.y);
            float mm = fminf(fminf(m01, m23), fminf(m45, m67));
            if (mm < thrE) {
                float tt[8] = {f01.x, f01.y, f23.x, f23.y, f45.x, f45.y, f67.x, f67.y};
                int ib = cbase + t0 + j;
#pragma unroll
                for (int uu = 0; uu < 8; uu++) {
                    sBuf[bbuf + cnt] = make_float2(tt[uu], __int_as_float(ib + uu));
                    cnt += (tt[uu] < thrE) ? 1 : 0;
                }
            }
            if (__any_sync(0xffffffffu, cnt >= BS - 7)) {
#pragma unroll 1
                for (int e = 0; e < cnt; e++) {
                    float2 pr = sBuf[bbuf + e];
                    if (pr.x < thrE) {
                        float ts = fmaxf(pr.x + qw, 0.f);
                        unsigned slot = worstP & 0xFu;
                        sVal[vb + slot] = (__float_as_uint(ts) & 0xFFFFFFF0u) | slot;
                        sIdx[vb + slot] = __float_as_int(pr.y);
                        unsigned mmax = 0u;
                        const uint4* vp = (const uint4*)(sVal + vb);
#pragma unroll
                        for (int s4 = 0; s4 < 4; s4++) {
                            uint4 v = vp[s4];
                            mmax = max(mmax, max(max(v.x, v.y), max(v.z, v.w)));
                        }
                        worstP = mmax;
                        thrLoc = __uint_as_float(mmax & 0xFFFFFFF0u) - qw;
                        thrE = fminf(thrE, thrLoc);
                    }
                }
                cnt = 0;
                sThr[wid * 32 + lane] = thrLoc;   // publish tightened local threshold
            }
        }
    }

    // final flush of buffered candidates
#pragma unroll 1
    for (int e = 0; e < cnt; e++) {
        float2 pr = sBuf[bbuf + e];
        if (pr.x < thrE) {
            float ts = fmaxf(pr.x + qw, 0.f);
            unsigned slot = worstP & 0xFu;
            sVal[vb + slot] = (__float_as_uint(ts) & 0xFFFFFFF0u) | slot;
            sIdx[vb + slot] = __float_as_int(pr.y);
            unsigned mmax = 0u;
            const uint4* vp = (const uint4*)(sVal + vb);
#pragma unroll
            for (int s4 = 0; s4 < 4; s4++) {
                uint4 v = vp[s4];
                mmax = max(mmax, max(max(v.x, v.y), max(v.z, v.w)));
            }
            worstP = mmax;
            thrLoc = __uint_as_float(mmax & 0xFFFFFFF0u) - qw;
            thrE = fminf(thrE, thrLoc);
        }
    }

    // tree merge: round 1: w0<-w2, w1<-w3 ; round 2: w0<-w1
    float thrts = __uint_as_float(worstP & 0xFFFFFFF0u);
    __syncthreads();
    if (wid < 2) {
        int pb = ((wid + 2) * 32 + lane) * VST;
#pragma unroll
        for (int s = 0; s < 16; s++) {
            unsigned pv = sVal[pb + s];
            float pvts = __uint_as_float(pv & 0xFFFFFFF0u);
            if (pvts < thrts) {
                unsigned slot = worstP & 0xFu;
                sVal[vb + slot] = (pv & 0xFFFFFFF0u) | slot;
                sIdx[vb + slot] = sIdx[pb + s];
                unsigned mmax = 0u;
                const uint4* vp = (const uint4*)(sVal + vb);
#pragma unroll
                for (int s4 = 0; s4 < 4; s4++) {
                    uint4 v = vp[s4];
                    mmax = max(mmax, max(max(v.x, v.y), max(v.z, v.w)));
                }
                worstP = mmax;
                thrts = __uint_as_float(mmax & 0xFFFFFFF0u);
            }
        }
    }
    __syncthreads();
    if (wid == 0) {
        int pb = (32 + lane) * VST;
#pragma unroll
        for (int s = 0; s < 16; s++) {
            unsigned pv = sVal[pb + s];
            float pvts = __uint_as_float(pv & 0xFFFFFFF0u);
            if (pvts < thrts) {
                unsigned slot = worstP & 0xFu;
                sVal[vb + slot] = (pv & 0xFFFFFFF0u) | slot;
                sIdx[vb + slot] = sIdx[pb + s];
                unsigned mmax = 0u;
                const uint4* vp = (const uint4*)(sVal + vb);
#pragma unroll
                for (int s4 = 0; s4 < 4; s4++) {
                    uint4 v = vp[s4];
                    mmax = max(mmax, max(max(v.x, v.y), max(v.z, v.w)));
                }
                worstP = mmax;
                thrts = __uint_as_float(mmax & 0xFFFFFFF0u);
            }
        }
#pragma unroll
        for (int s = 0; s < 16; s++) g_NB[p * KK + s] = sIdx[vb + s];
    }
}

// ---------------- k2: per-point transforms, 3 passes of 64 outs -----------------
__global__ void __launch_bounds__(256) k2(const float* __restrict__ feats,
                   const float* __restrict__ W1, const float* __restrict__ b1,
                   const float* __restrict__ Wv, const float* __restrict__ bv) {
    __shared__ float sW[64][64];
    __shared__ float sF[64][64];
    int tid = threadIdx.x;
    int blk = blockIdx.x;
    int b   = blk >> 7;
    int n0  = (blk & 127) << 6;

    for (int e = tid; e < 1024; e += 256) {
        int c = e >> 4, v4 = e & 15;
        ((float4*)sF[c])[v4] =
            ((const float4*)(feats + (size_t)b * CC * NN + (size_t)c * NN + n0))[v4];
    }

    int og = tid & 15, ng = tid >> 4;

    for (int pp = 0; pp < 3; pp++) {
        __syncthreads();
        for (int e = tid; e < 4096; e += 256) {
            int ol = e & 63, c = e >> 6;
            float w;
            if (pp == 0)      w = W1[ol * 131 + c];
            else if (pp == 1) w = W1[ol * 131 + 64 + c];
            else              w = Wv[ol * 67 + c];
            sW[c][ol] = w;
        }
        __syncthreads();

        float4 a0 = make_float4(0.f,0.f,0.f,0.f), a1 = a0, a2 = a0, a3 = a0;
        for (int c = 0; c < 64; c++) {
            float4 w4 = *(const float4*)&sW[c][og * 4];
            float4 f4 = *(const float4*)&sF[c][ng * 4];
            a0.x = fmaf(w4.x, f4.x, a0.x); a0.y = fmaf(w4.y, f4.x, a0.y);
            a0.z = fmaf(w4.z, f4.x, a0.z); a0.w = fmaf(w4.w, f4.x, a0.w);
            a1.x = fmaf(w4.x, f4.y, a1.x); a1.y = fmaf(w4.y, f4.y, a1.y);
            a1.z = fmaf(w4.z, f4.y, a1.z); a1.w = fmaf(w4.w, f4.y, a1.w);
            a2.x = fmaf(w4.x, f4.z, a2.x); a2.y = fmaf(w4.y, f4.z, a2.y);
            a2.z = fmaf(w4.z, f4.z, a2.z); a2.w = fmaf(w4.w, f4.z, a2.w);
            a3.x = fmaf(w4.x, f4.w, a3.x); a3.y = fmaf(w4.y, f4.w, a3.y);
            a3.z = fmaf(w4.z, f4.w, a3.z); a3.w = fmaf(w4.w, f4.w, a3.w);
        }

        float4 bb = make_float4(0.f, 0.f, 0.f, 0.f);
        if (pp == 0) bb = *(const float4*)(b1 + og * 4);
        if (pp == 2) bb = *(const float4*)(bv + og * 4);
        int obase = pp * 64 + og * 4;
        float4 r;
        size_t pbase = (size_t)(b * NN + n0 + ng * 4);
        r = make_float4(a0.x+bb.x, a0.y+bb.y, a0.z+bb.z, a0.w+bb.w);
        *(float4*)(g_PT + (pbase + 0) * 192 + obase) = r;
        r = make_float4(a1.x+bb.x, a1.y+bb.y, a1.z+bb.z, a1.w+bb.w);
        *(float4*)(g_PT + (pbase + 1) * 192 + obase) = r;
        r = make_float4(a2.x+bb.x, a2.y+bb.y, a2.z+bb.z, a2.w+bb.w);
        *(float4*)(g_PT + (pbase + 2) * 192 + obase) = r;
        r = make_float4(a3.x+bb.x, a3.y+bb.y, a3.z+bb.z, a3.w+bb.w);
        *(float4*)(g_PT + (pbase + 3) * 192 + obase) = r;
    }
}

// ---------------- k3: BN stats for h and v (f32x2, channel pairs) ---------------
__global__ void __launch_bounds__(256) k3(const float* __restrict__ W1,
                                          const float* __restrict__ Wv) {
    __shared__ float sstat[256];
    int tid = threadIdx.x, lane = tid & 31, wid = tid >> 5;
    for (int e = tid; e < 256; e += 256) sstat[e] = 0.f;
    __syncthreads();

    int cc = lane * 2;   // channels cc, cc+1
    u64 w1x0 = pkab(W1[cc * 131 + 128], W1[(cc + 1) * 131 + 128]);
    u64 w1x1 = pkab(W1[cc * 131 + 129], W1[(cc + 1) * 131 + 129]);
    u64 w1x2 = pkab(W1[cc * 131 + 130], W1[(cc + 1) * 131 + 130]);
    u64 wvx0 = pkab(Wv[cc * 67 + 64],  Wv[(cc + 1) * 67 + 64]);
    u64 wvx1 = pkab(Wv[cc * 67 + 65],  Wv[(cc + 1) * 67 + 65]);
    u64 wvx2 = pkab(Wv[cc * 67 + 66],  Wv[(cc + 1) * 67 + 66]);

    u64 sh = 0, shq = 0, sv = 0, svq = 0;
    int gw = blockIdx.x * 8 + wid, nw = gridDim.x * 8;
    for (int p = gw; p < NPTS; p += nw) {
        int b = p >> 13;
        float4 q = g_P4[p];
        const int4* nb = (const int4*)(g_NB + p * KK);
        int4 iA = nb[0], iB = nb[1], iC = nb[2], iD = nb[3];
        int mi[16] = {iA.x, iA.y, iA.z, iA.w, iB.x, iB.y, iB.z, iB.w,
                      iC.x, iC.y, iC.z, iC.w, iD.x, iD.y, iD.z, iD.w};
        const float* ptp = g_PT + (size_t)p * 192;
        u64 hcp = *(const u64*)(ptp + cc);
#pragma unroll
        for (int k = 0; k < KK; k++) {
            int m = mi[k];
            float4 pm = g_P4[b * NN + m];
            u64 rxp = pk2(pm.x - q.x), ryp = pk2(pm.y - q.y), rzp = pk2(pm.z - q.z);
            const float* ptm = g_PT + (size_t)(b * NN + m) * 192;
            u64 hnp = *(const u64*)(ptm + 64 + cc);
            u64 vnp = *(const u64*)(ptm + 128 + cc);
            u64 h = fma2(rzp, w1x2, fma2(ryp, w1x1, fma2(rxp, w1x0, add2(hcp, hnp))));
            u64 v = fma2(rzp, wvx2, fma2(ryp, wvx1, fma2(rxp, wvx0, vnp)));
            sh = add2(sh, h); shq = fma2(h, h, shq);
            sv = add2(sv, v); svq = fma2(v, v, svq);
        }
    }
    float2 fsh = unpk(sh), fshq = unpk(shq), fsv = unpk(sv), fsvq = unpk(svq);
    atomicAdd(&sstat[cc], fsh.x);       atomicAdd(&sstat[cc + 1], fsh.y);
    atomicAdd(&sstat[64 + cc], fshq.x); atomicAdd(&sstat[64 + cc + 1], fshq.y);
    atomicAdd(&sstat[128 + cc], fsv.x); atomicAdd(&sstat[128 + cc + 1], fsv.y);
    atomicAdd(&sstat[192 + cc], fsvq.x);atomicAdd(&sstat[192 + cc + 1], fsvq.y);
    __syncthreads();
    for (int e = tid; e < 256; e += 256) atomicAdd(&g_stats[e], sstat[e]);
}

// ---------------- k5: attention + value + out-conv (vectorized Wo epilogue) -----
__global__ void __launch_bounds__(256) k5(const float* __restrict__ W1,
                   const float* __restrict__ Wv,
                   const float* __restrict__ W2, const float* __restrict__ b2,
                   const float* __restrict__ Wo, const float* __restrict__ bo,
                   const float* __restrict__ g1, const float* __restrict__ be1,
                   const float* __restrict__ gv, const float* __restrict__ bev) {
    __shared__ __align__(16) u64 sWoP[64][33];   // sWoP[j][lane] = (Wo[2l][j], Wo[2l+1][j])
    __shared__ __align__(16) float sOut[8][64];
    __shared__ float sstat[128];
    int tid = threadIdx.x, lane = tid & 31, wid = tid >> 5;

    for (int e = tid; e < 64 * 32; e += 256) {
        int j = e >> 5, l = e & 31;
        sWoP[j][l] = pkab(Wo[(2 * l) * 64 + j], Wo[(2 * l + 1) * 64 + j]);
    }
    for (int e = tid; e < 128; e += 256) sstat[e] = 0.f;

    int cc = lane * 2;
    u64 w1x0 = pkab(W1[cc * 131 + 128], W1[(cc + 1) * 131 + 128]);
    u64 w1x1 = pkab(W1[cc * 131 + 129], W1[(cc + 1) * 131 + 129]);
    u64 w1x2 = pkab(W1[cc * 131 + 130], W1[(cc + 1) * 131 + 130]);
    u64 wvx0 = pkab(Wv[cc * 67 + 64],  Wv[(cc + 1) * 67 + 64]);
    u64 wvx1 = pkab(Wv[cc * 67 + 65],  Wv[(cc + 1) * 67 + 65]);
    u64 wvx2 = pkab(Wv[cc * 67 + 66],  Wv[(cc + 1) * 67 + 66]);

    // BN coefficients computed from finalized g_stats (k4 folded in)
    float cntk = (float)((size_t)NPTS * KK);
    float mh1 = g_stats[cc] / cntk,     mh2 = g_stats[cc + 1] / cntk;
    float vh1 = g_stats[64 + cc] / cntk - mh1 * mh1;
    float vh2 = g_stats[64 + cc + 1] / cntk - mh2 * mh2;
    float a1a = g1[cc] * rsqrtf(vh1 + 1e-5f), a1b = g1[cc + 1] * rsqrtf(vh2 + 1e-5f);
    float d1a = be1[cc] - a1a * mh1,          d1b = be1[cc + 1] - a1b * mh2;
    float mv1 = g_stats[128 + cc] / cntk,     mv2 = g_stats[128 + cc + 1] / cntk;
    float vv1s = g_stats[192 + cc] / cntk - mv1 * mv1;
    float vv2s = g_stats[192 + cc + 1] / cntk - mv2 * mv2;
    float ava = gv[cc] * rsqrtf(vv1s + 1e-5f), avb = gv[cc + 1] * rsqrtf(vv2s + 1e-5f);
    float dva = bev[cc] - ava * mv1,           dvb = bev[cc + 1] - avb * mv2;

    float w2a = W2[cc], w2b = W2[cc + 1];
    float b2v = b2[0];
    u64 boP = pkab(bo[cc], bo[cc + 1]);
    __syncthreads();

    float so1 = 0.f, so1q = 0.f, so2 = 0.f, so2q = 0.f;
    int gw = blockIdx.x * 8 + wid, nw = gridDim.x * 8;

    for (int p = gw; p < NPTS; p += nw) {
        int b = p >> 13;
        float4 q = g_P4[p];
        const int4* nb = (const int4*)(g_NB + p * KK);
        int4 iA = nb[0], iB = nb[1], iC = nb[2], iD = nb[3];
        int mi[16] = {iA.x, iA.y, iA.z, iA.w, iB.x, iB.y, iB.z, iB.w,
                      iC.x, iC.y, iC.z, iC.w, iD.x, iD.y, iD.z, iD.w};
        const float* ptp = g_PT + (size_t)p * 192;
        u64 hcp = *(const u64*)(ptp + cc);

        float logits[KK], vv1[KK], vv2[KK];
#pragma unroll
        for (int k = 0; k < KK; k++) {
            int m = mi[k];
            float4 pm = g_P4[b * NN + m];
            u64 rxp = pk2(pm.x - q.x), ryp = pk2(pm.y - q.y), rzp = pk2(pm.z - q.z);
            const float* ptm = g_PT + (size_t)(b * NN + m) * 192;
            u64 hnp = *(const u64*)(ptm + 64 + cc);
            u64 vnp = *(const u64*)(ptm + 128 + cc);
            u64 h = fma2(rzp, w1x2, fma2(ryp, w1x1, fma2(rxp, w1x0, add2(hcp, hnp))));
            u64 v = fma2(rzp, wvx2, fma2(ryp, wvx1, fma2(rxp, wvx0, vnp)));
            float2 hf = unpk(h), vf = unpk(v);
            float hb1 = fmaxf(a1a * hf.x + d1a, 0.f);
            float hb2 = fmaxf(a1b * hf.y + d1b, 0.f);
            vv1[k] = fmaxf(ava * vf.x + dva, 0.f);
            vv2[k] = fmaxf(avb * vf.y + dvb, 0.f);
            float t = hb1 * w2a + hb2 * w2b;
#pragma unroll
            for (int off = 16; off > 0; off >>= 1) t += __shfl_xor_sync(0xffffffffu, t, off);
            logits[k] = t + b2v;
        }
        float mx = logits[0];
#pragma unroll
        for (int k = 1; k < KK; k++) mx = fmaxf(mx, logits[k]);
        float ex[KK], se = 0.f;
#pragma unroll
        for (int k = 0; k < KK; k++) { ex[k] = __expf(logits[k] - mx); se += ex[k]; }
        float inv = 1.0f / se;
        float out1 = 0.f, out2 = 0.f;
#pragma unroll
        for (int k = 0; k < KK; k++) {
            float w = ex[k] * inv;
            out1 += w * vv1[k];
            out2 += w * vv2[k];
        }
        __syncwarp();
        *(float2*)&sOut[wid][cc] = make_float2(out1, out2);
        __syncwarp();
        // vectorized Wo epilogue: broadcast LDS.128 of sOut + per-lane u64 Wo pairs
        u64 oo = boP;
#pragma unroll
        for (int j4 = 0; j4 < 16; j4++) {
            float4 o4 = *(const float4*)&sOut[wid][j4 * 4];
            oo = fma2(pk2(o4.x), sWoP[j4 * 4 + 0][lane], oo);
            oo = fma2(pk2(o4.y), sWoP[j4 * 4 + 1][lane], oo);
            oo = fma2(pk2(o4.z), sWoP[j4 * 4 + 2][lane], oo);
            oo = fma2(pk2(o4.w), sWoP[j4 * 4 + 3][lane], oo);
        }
        float2 oof = unpk(oo);
        *(float2*)(g_Opre + (size_t)p * 64 + cc) = oof;
        so1 += oof.x; so1q += oof.x * oof.x;
        so2 += oof.y; so2q += oof.y * oof.y;
    }
    atomicAdd(&sstat[cc], so1);     atomicAdd(&sstat[64 + cc], so1q);
    atomicAdd(&sstat[cc + 1], so2); atomicAdd(&sstat[64 + cc + 1], so2q);
    __syncthreads();
    for (int e = tid; e < 128; e += 256) atomicAdd(&g_ostats[e], sstat[e]);
}

// ---------------- k7: BN + relu + residual + transpose (k6 folded in) -----------
__global__ void k7(const float* __restrict__ feats, float* __restrict__ out,
                   const float* __restrict__ go, const float* __restrict__ beo) {
    __shared__ float tile[32][65];
    __shared__ float sco[128];
    int blk = blockIdx.x;
    int b = blk >> 8;
    int n0 = (blk & 255) << 5;
    int tid = threadIdx.x;
    if (tid < 64) {
        float cntp = (float)NPTS;
        float m = g_ostats[tid] / cntp;
        float v = g_ostats[64 + tid] / cntp - m * m;
        float a = go[tid] * rsqrtf(v + 1e-5f);
        sco[tid] = a; sco[64 + tid] = beo[tid] - a * m;
    }
    for (int e = tid; e < 32 * 64; e += 256) {
        int pp = e >> 6, c = e & 63;
        tile[pp][c] = g_Opre[(size_t)(b * NN + n0 + pp) * 64 + c];
    }
    __syncthreads();
    for (int e = tid; e < 64 * 32; e += 256) {
        int c = e >> 5, j = e & 31;
        float val = sco[c] * tile[j][c] + sco[64 + c];
        val = fmaxf(val, 0.f) + feats[(size_t)b * CC * NN + (size_t)c * NN + n0 + j];
        out[(size_t)b * CC * NN + (size_t)c * NN + n0 + j] = val;
    }
}

// ---------------- launch --------------------------------------------------------
extern "C" void kernel_launch(void* const* d_in, const int* in_sizes, int n_in,
                              void* d_out, int out_size) {
    const float* xyz   = (const float*)d_in[0];
    const float* feats = (const float*)d_in[1];
    const float* W1    = (const float*)d_in[2];
    const float* b1    = (const float*)d_in[3];
    const float* g1    = (const float*)d_in[4];
    const float* be1   = (const float*)d_in[5];
    const float* W2    = (const float*)d_in[6];
    const float* b2    = (const float*)d_in[7];
    const float* Wv    = (const float*)d_in[8];
    const float* bv    = (const float*)d_in[9];
    const float* gv    = (const float*)d_in[10];
    const float* bev   = (const float*)d_in[11];
    const float* Wo    = (const float*)d_in[12];
    const float* bo    = (const float*)d_in[13];
    const float* go    = (const float*)d_in[14];
    const float* beo   = (const float*)d_in[15];
    float* out = (float*)d_out;

    // lazily-created side stream + events (no device memory involved)
    static cudaStream_t s2 = nullptr;
    static cudaEvent_t evFork = nullptr, evJoin = nullptr;
    if (s2 == nullptr) {
        cudaStreamCreateWithFlags(&s2, cudaStreamNonBlocking);
        cudaEventCreateWithFlags(&evFork, cudaEventDisableTiming);
        cudaEventCreateWithFlags(&evJoin, cudaEventDisableTiming);
    }

    // fork: k2 (depends only on feats) runs concurrently with k0+k1
    cudaEventRecord(evFork, 0);
    cudaStreamWaitEvent(s2, evFork, 0);
    k2<<<NPTS / 64, 256, 0, s2>>>(feats, W1, b1, Wv, bv);
    cudaEventRecord(evJoin, s2);

    k0<<<NPTS / 256, 256>>>(xyz);
    k1<<<NPTS / 32, 128>>>();

    // join: k3 needs both k1 (g_NB) and k2 (g_PT)
    cudaStreamWaitEvent(0, evJoin, 0);
    k3<<<1184, 256>>>(W1, Wv);
    k5<<<1184, 256>>>(W1, Wv, W2, b2, Wo, bo, g1, be1, gv, bev);
    k7<<<NPTS / 32, 256>>>(feats, out, go, beo);
}